// round 1
// baseline (speedup 1.0000x reference)
#include <cuda_runtime.h>

// WindowEmbedding forward: out[b, t, k*D + d] = (t-k >= 0) ? in[b, t-k, d] : 0
// Shapes fixed by the problem: B=16, T=2048, D=256, W=7.
// Pure bandwidth problem: ~235 MB stores + ~33.5 MB loads (input fits in L2).

#define B_DIM 16
#define T_DIM 2048
#define D_DIM 256
#define W_DIM 7

#define D4 (D_DIM / 4)          // 64 float4 per row
#define SLICE4 (W_DIM * D4)     // 448 float4 per (b,t) output row

__global__ __launch_bounds__(SLICE4) void window_embed_kernel(
    const float4* __restrict__ in,   // [B, T, D] as float4: [B, T, 64]
    float4* __restrict__ out)        // [B, T, W*D] as float4: [B, T, 448]
{
    const int bt  = blockIdx.x;          // 0 .. B*T-1
    const int t   = bt & (T_DIM - 1);    // T is power of 2
    const int tid = threadIdx.x;         // 0 .. 447
    const int k   = tid >> 6;            // which shift (0..6)
    const int d4  = tid & 63;            // float4 column within row

    const int ts = t - k;                // source time index
    float4 v = make_float4(0.f, 0.f, 0.f, 0.f);
    if (ts >= 0) {
        // in[b, ts, d4] ; (bt - k) == b*T + ts since ts >= 0 stays in same batch
        v = in[(long long)(bt - k) * D4 + d4];
    }
    out[(long long)bt * SLICE4 + tid] = v;
}

extern "C" void kernel_launch(void* const* d_in, const int* in_sizes, int n_in,
                              void* d_out, int out_size)
{
    const float4* in = (const float4*)d_in[0];
    float4* out = (float4*)d_out;

    dim3 grid(B_DIM * T_DIM);
    dim3 block(SLICE4);
    window_embed_kernel<<<grid, block>>>(in, out);
}

// round 3
// speedup vs baseline: 1.4945x; 1.4945x over previous
#include <cuda_runtime.h>

// WindowEmbedding forward: out[b, t, k*D + d] = (t-k >= 0) ? in[b, t-k, d] : 0
// B=16, T=2048, D=256, W=7. Pure bandwidth: 235 MB stores, 33.5 MB reads (L2-resident).
// R2: 8 t-values per thread -> MLP=8 per thread, batched loads then stores,
//     streaming stores to protect input's L2 residency.

#define B_DIM 16
#define T_DIM 2048
#define D_DIM 256
#define W_DIM 7

#define D4 (D_DIM / 4)          // 64 float4 per input row
#define SLICE4 (W_DIM * D4)     // 448 float4 per output row
#define TILE_T 8                // t-values per thread

__global__ __launch_bounds__(SLICE4) void window_embed_kernel(
    const float4* __restrict__ in,   // [B, T, 64] float4
    float4* __restrict__ out)        // [B, T, 448] float4
{
    const int bt0 = blockIdx.x * TILE_T;     // base (b*T + t0), t0 multiple of 8
    const int t0  = bt0 & (T_DIM - 1);
    const int tid = threadIdx.x;             // 0..447
    const int k   = tid >> 6;                // shift 0..6
    const int d4  = tid & 63;                // float4 column

    const float4* src = in  + (long long)(bt0 - k) * D4 + d4;
    float4*       dst = out + (long long)bt0 * SLICE4 + tid;

    float4 v[TILE_T];

    if (t0 >= W_DIM - 1) {
        // Fast path: all source indices valid (t0 - k >= t0 - 6 >= 0).
        #pragma unroll
        for (int j = 0; j < TILE_T; j++)
            v[j] = src[j * D4];
        #pragma unroll
        for (int j = 0; j < TILE_T; j++)
            __stcs(&dst[j * SLICE4], v[j]);
    } else {
        // Only blocks with t0 == 0 (16 of 4096) hit this.
        #pragma unroll
        for (int j = 0; j < TILE_T; j++) {
            const int ts = t0 + j - k;
            v[j] = (ts >= 0) ? src[j * D4] : make_float4(0.f, 0.f, 0.f, 0.f);
        }
        #pragma unroll
        for (int j = 0; j < TILE_T; j++)
            __stcs(&dst[j * SLICE4], v[j]);
    }
}

extern "C" void kernel_launch(void* const* d_in, const int* in_sizes, int n_in,
                              void* d_out, int out_size)
{
    const float4* in = (const float4*)d_in[0];
    float4* out = (float4*)d_out;

    dim3 grid(B_DIM * T_DIM / TILE_T);   // 4096
    dim3 block(SLICE4);                  // 448
    window_embed_kernel<<<grid, block>>>(in, out);
}

// round 4
// speedup vs baseline: 1.4969x; 1.0016x over previous
#include <cuda_runtime.h>

// WindowEmbedding forward: out[b, t, k*D + d] = (t-k >= 0) ? in[b, t-k, d] : 0
// B=16, T=2048, D=256, W=7.
// R3: shared-memory staging. Each block stages 22 input rows (16 + 6 halo) in
// smem ONCE, then fans out 7 shifted copies from LDS. Cuts L2 read traffic 7x
// (was the binding constraint: 470 MB L2 traffic ~= measured 39.7us at LTS cap).

#define B_DIM 16
#define T_DIM 2048
#define D_DIM 256
#define W_DIM 7

#define D4 (D_DIM / 4)            // 64 float4 per input row
#define SLICE4 (W_DIM * D4)       // 448 float4 per output row
#define TILE_T 16                 // t-values per block
#define HALO (W_DIM - 1)          // 6
#define ROWS (TILE_T + HALO)      // 22 staged rows
#define NTHREADS SLICE4           // 448

__global__ __launch_bounds__(NTHREADS) void window_embed_kernel(
    const float4* __restrict__ in,   // [B, T, 64] float4
    float4* __restrict__ out)        // [B, T, 448] float4
{
    __shared__ float4 s[ROWS * D4];  // 22 * 64 * 16B = 22528 B

    const int bt0 = blockIdx.x * TILE_T;     // b*T + t0, t0 multiple of 16
    const int t0  = bt0 & (T_DIM - 1);
    const int tid = threadIdx.x;             // 0..447

    // Stage rows (t0-6 .. t0+15) into smem, zero-filling t < 0.
    // (bt0 - HALO + r) == b*T + (t0 - HALO + r) whenever t0-HALO+r >= 0.
    const float4 zero = make_float4(0.f, 0.f, 0.f, 0.f);
    #pragma unroll
    for (int i = tid; i < ROWS * D4; i += NTHREADS) {
        const int r  = i >> 6;               // staged row 0..21
        const int ts = t0 - HALO + r;        // source time index
        s[i] = (ts >= 0) ? in[(long long)(bt0 - HALO + r) * D4 + (i & 63)]
                         : zero;
    }
    __syncthreads();

    // Fan out: out[t0+j][k*64 + d4] = s[(j + 6 - k)*64 + d4]
    const int k  = tid >> 6;                 // shift 0..6
    const int d4 = tid & 63;
    const float4* srow = &s[(HALO - k) * D4 + d4];
    float4* dst = out + (long long)bt0 * SLICE4 + tid;

    #pragma unroll
    for (int j = 0; j < TILE_T; j++)
        __stcs(&dst[j * SLICE4], srow[j * D4]);
}

extern "C" void kernel_launch(void* const* d_in, const int* in_sizes, int n_in,
                              void* d_out, int out_size)
{
    const float4* in = (const float4*)d_in[0];
    float4* out = (float4*)d_out;

    dim3 grid(B_DIM * T_DIM / TILE_T);   // 2048
    dim3 block(NTHREADS);                // 448
    window_embed_kernel<<<grid, block>>>(in, out);
}